// round 1
// baseline (speedup 1.0000x reference)
#include <cuda_runtime.h>

#define NB 2
#define DD 160
#define HH 192
#define WW 224
#define SLICE (HH*WW)          // 43008
#define VOL   (DD*SLICE)       // 6881280
#define TOT   (NB*VOL)         // 13762560

// 275 MB scratch for the 5 W+H-blurred channels, channel-major.
__device__ float  g_mid[5u * TOT];
__device__ double g_sum[2];

#define W0 0.05448868454964294f
#define W1 0.24420134200323332f
#define W2 0.40261994689424753f

// ---------------------------------------------------------------------------
// Kernel A: per (n,d) slice, fused W-blur + H-blur of the 5 channels
// (I, J, I*J, I*I, J*J). 32x32 output tile, 2-voxel halo, zero padding.
// ---------------------------------------------------------------------------
__global__ void __launch_bounds__(256) lncc_blur_wh(const float* __restrict__ I,
                                                    const float* __restrict__ J)
{
    __shared__ float sch[5][36][36];   // raw channels with halo
    __shared__ float stmp[36][32];     // W-blurred, halo in H only

    const int tid = threadIdx.x;
    const int nd  = blockIdx.z;                 // n*DD + d
    const int gx0 = blockIdx.x * 32;
    const int gy0 = blockIdx.y * 32;

    const float* __restrict__ Ib = I + (size_t)nd * SLICE;
    const float* __restrict__ Jb = J + (size_t)nd * SLICE;

    // Load halo region, compute 5 channels.
    for (int i = tid; i < 36 * 36; i += 256) {
        int ly = i / 36, lx = i - ly * 36;
        int gy = gy0 + ly - 2, gx = gx0 + lx - 2;
        float a = 0.f, b = 0.f;
        if (gy >= 0 && gy < HH && gx >= 0 && gx < WW) {
            int o = gy * WW + gx;
            a = Ib[o];
            b = Jb[o];
        }
        sch[0][ly][lx] = a;
        sch[1][ly][lx] = b;
        sch[2][ly][lx] = a * b;
        sch[3][ly][lx] = a * a;
        sch[4][ly][lx] = b * b;
    }
    __syncthreads();

    const size_t obase = (size_t)nd * SLICE;   // == n*VOL + d*SLICE

    #pragma unroll
    for (int c = 0; c < 5; c++) {
        // W blur: 36 rows x 32 cols
        for (int i = tid; i < 36 * 32; i += 256) {
            int ly = i >> 5, lx = i & 31;
            float s = W0 * (sch[c][ly][lx]     + sch[c][ly][lx + 4])
                    + W1 * (sch[c][ly][lx + 1] + sch[c][ly][lx + 3])
                    + W2 *  sch[c][ly][lx + 2];
            stmp[ly][lx] = s;
        }
        __syncthreads();
        // H blur + store: 32 x 32 outputs
        for (int i = tid; i < 32 * 32; i += 256) {
            int ly = i >> 5, lx = i & 31;
            float s = W0 * (stmp[ly][lx]     + stmp[ly + 4][lx])
                    + W1 * (stmp[ly + 1][lx] + stmp[ly + 3][lx])
                    + W2 *  stmp[ly + 2][lx];
            g_mid[(size_t)c * TOT + obase + (size_t)(gy0 + ly) * WW + (gx0 + lx)] = s;
        }
        __syncthreads();
    }
}

// ---------------------------------------------------------------------------
// Kernel B: D-blur (float4 vectorized) + LNCC + masked reduction.
// ---------------------------------------------------------------------------
__global__ void __launch_bounds__(256) lncc_blur_d_reduce(const float* __restrict__ M)
{
    const int idx4 = blockIdx.x * 256 + threadIdx.x;
    float sl = 0.f, sm = 0.f;

    if (idx4 < TOT / 4) {
        const int v   = idx4 * 4;
        const int n   = v / VOL;
        const int rem = v - n * VOL;
        const int d   = rem / SLICE;
        const int p   = rem - d * SLICE;

        const float w[5] = {W0, W1, W2, W1, W0};

        float A[5][4];
        #pragma unroll
        for (int c = 0; c < 5; c++) {
            A[c][0] = A[c][1] = A[c][2] = A[c][3] = 0.f;
        }

        #pragma unroll
        for (int t = 0; t < 5; t++) {
            int dz = d + t - 2;
            if (dz >= 0 && dz < DD) {
                const size_t off = (size_t)n * VOL + (size_t)dz * SLICE + p;
                const float wt = w[t];
                #pragma unroll
                for (int c = 0; c < 5; c++) {
                    const float4 x = *reinterpret_cast<const float4*>(
                        &g_mid[(size_t)c * TOT + off]);
                    A[c][0] += wt * x.x;
                    A[c][1] += wt * x.y;
                    A[c][2] += wt * x.z;
                    A[c][3] += wt * x.w;
                }
            }
        }

        const float4 mk4 = *reinterpret_cast<const float4*>(&M[v]);
        const float mk[4] = {mk4.x, mk4.y, mk4.z, mk4.w};

        #pragma unroll
        for (int k = 0; k < 4; k++) {
            float bI  = A[0][k], bJ = A[1][k];
            float bIJ = A[2][k], bII = A[3][k], bJJ = A[4][k];
            float cross = bIJ - bI * bJ;
            float varI  = fmaxf(bII - bI * bI, 0.f) + 1e-5f;
            float varJ  = fmaxf(bJJ - bJ * bJ, 0.f) + 1e-5f;
            float lncc  = 1.f - cross * rsqrtf(varI * varJ);
            sl += lncc * mk[k];
            sm += mk[k];
        }
    }

    // Warp reduce
    #pragma unroll
    for (int o = 16; o > 0; o >>= 1) {
        sl += __shfl_down_sync(0xFFFFFFFFu, sl, o);
        sm += __shfl_down_sync(0xFFFFFFFFu, sm, o);
    }
    __shared__ float rl[8], rm[8];
    const int lane = threadIdx.x & 31, wid = threadIdx.x >> 5;
    if (lane == 0) { rl[wid] = sl; rm[wid] = sm; }
    __syncthreads();
    if (threadIdx.x == 0) {
        float tl = 0.f, tm = 0.f;
        #pragma unroll
        for (int i = 0; i < 8; i++) { tl += rl[i]; tm += rm[i]; }
        atomicAdd(&g_sum[0], (double)tl);
        atomicAdd(&g_sum[1], (double)tm);
    }
}

__global__ void lncc_init()
{
    g_sum[0] = 0.0;
    g_sum[1] = 0.0;
}

__global__ void lncc_final(float* __restrict__ out)
{
    out[0] = (float)(g_sum[0] / (g_sum[1] + 1e-8));
}

// ---------------------------------------------------------------------------

extern "C" void kernel_launch(void* const* d_in, const int* in_sizes, int n_in,
                              void* d_out, int out_size)
{
    const float* A = (const float*)d_in[0];  // image_A
    const float* B = (const float*)d_in[1];  // image_B
    const float* M = (const float*)d_in[2];  // mask_A
    float* out = (float*)d_out;

    lncc_init<<<1, 1>>>();

    dim3 gA(WW / 32, HH / 32, NB * DD);      // (7, 6, 320)
    lncc_blur_wh<<<gA, 256>>>(A, B);

    const int nblk = (TOT / 4 + 255) / 256;  // 13440
    lncc_blur_d_reduce<<<nblk, 256>>>(M);

    lncc_final<<<1, 1>>>(out);
}